// round 14
// baseline (speedup 1.0000x reference)
#include <cuda_runtime.h>

// MIND loss, 1024x1024, round 14 = R8 exactly, with __launch_bounds__(256,7).
//  - 72/80 channels identical; uniform tiles need only 4 distinct channels
//  - staged basis planes -> ring vertical conv (240 scalar threads)
//    -> horizontal conv + combine
//  - SINGLE CHANGE vs R8: occupancy 6 -> 7 blocks/SM (forces regs<=36);
//    tests whether register-capped residency is the latency-bound limiter
//  - general path (105/1118 blocks): staged scheme, dedicated spare region
//  - deterministic shuffle reductions, fused last-block finish

#define TX 40
#define TY 24
#define NBX 26
#define NBY 43
#define NBLK (NBX * NBY)

#define PITCH 48
#define RIN   30
#define PSTR  1456              // 30*48 + 16
#define SPARE0 (5 * PSTR)       // a2t mixed rows (6 x 48)
#define SPARE1 (5 * PSTR + 288) // a3t mixed rows
#define SMEMN  (5 * PSTR + 576)

#define CW(k) ((k)==0 ? 0.06475879783294587f : \
               (k)==1 ? 0.12098536225957168f : \
               (k)==2 ? 0.17603266338214976f : \
               (k)==3 ? 0.19947114020071635f : \
               (k)==4 ? 0.17603266338214976f : \
               (k)==5 ? 0.12098536225957168f : \
                        0.06475879783294587f)

__device__ float g_partials[NBLK];
__device__ unsigned int g_count;

__device__ __forceinline__ float ex2(float x) {
    float r;
    asm("ex2.approx.ftz.f32 %0, %1;" : "=f"(r) : "f"(x));
    return r;
}

__global__ __launch_bounds__(256, 7)
void mind_main(const float* __restrict__ img1, const float* __restrict__ img2,
               float* __restrict__ out) {
    __shared__ __align__(16) float sraw[SMEMN];   // 31424 B
    __shared__ float swr[8];
    __shared__ bool s_last;

    const int tid = threadIdx.x;
    const int bx0 = 7 + blockIdx.x * TX;
    const int by0 = 7 + blockIdx.y * TY;

    // mask-uniformity over taps actually used (cols cc<=45, staged rows i<=29)
    const bool xu = !((bx0 - 3) < 512 && (bx0 + 42) >= 512);
    const bool yu = !((by0 - 3) < 512 && (by0 + 26) >= 512);

    float psum = 0.f;

    // ================= Stage basis fields (both paths) =================
    for (int i = tid; i < RIN * 12; i += 256) {
        const int row = i / 12;
        const int c4 = (i - row * 12) * 4;
        const int gy = by0 - 3 + row;
        const int gx = bx0 - 3 + c4;
        const int yo = gy ^ 512;
        const int xo = gx ^ 512;
        float4 v0 = {0,0,0,0}, v1 = v0, v2 = v0, v3 = v0, v4 = v0;
        if (gy < 1024) {
            if (gx + 3 < 1024) {
                float4 A  = *(const float4*)(img2 + gy * 1024 + gx);
                float4 B  = *(const float4*)(img2 + gy * 1024 + xo);
                float4 C  = *(const float4*)(img2 + yo * 1024 + gx);
                float4 D  = *(const float4*)(img2 + yo * 1024 + xo);
                float4 P  = *(const float4*)(img1 + gy * 1024 + gx);
                float4 Px = *(const float4*)(img1 + gy * 1024 + xo);
                float4 Py = *(const float4*)(img1 + yo * 1024 + gx);
                float t, u, w;
                v0.x = A.x * A.x; v0.y = A.y * A.y; v0.z = A.z * A.z; v0.w = A.w * A.w;
                t = A.x - B.x; v1.x = t * t - v0.x;  t = A.y - B.y; v1.y = t * t - v0.y;
                t = A.z - B.z; v1.z = t * t - v0.z;  t = A.w - B.w; v1.w = t * t - v0.w;
                t = A.x - C.x; v2.x = t * t - v0.x;  t = A.y - C.y; v2.y = t * t - v0.y;
                t = A.z - C.z; v2.z = t * t - v0.z;  t = A.w - C.w; v2.w = t * t - v0.w;
                t = A.x - D.x; v3.x = t * t - v0.x;  t = A.y - D.y; v3.y = t * t - v0.y;
                t = A.z - D.z; v3.z = t * t - v0.z;  t = A.w - D.w; v3.w = t * t - v0.w;
                u = P.x - Px.x; w = P.x - Py.x; v4.x = u * u + w * w + 2.f * P.x * P.x;
                u = P.y - Px.y; w = P.y - Py.y; v4.y = u * u + w * w + 2.f * P.y * P.y;
                u = P.z - Px.z; w = P.z - Py.z; v4.z = u * u + w * w + 2.f * P.z * P.z;
                u = P.w - Px.w; w = P.w - Py.w; v4.w = u * u + w * w + 2.f * P.w * P.w;
            } else {
                float r0[4], r1[4], r2[4], r3[4], r4[4];
#pragma unroll
                for (int e = 0; e < 4; e++) {
                    int x = gx + e;
                    r0[e] = r1[e] = r2[e] = r3[e] = r4[e] = 0.f;
                    if (x < 1024) {
                        int xe = x ^ 512;
                        float a  = img2[gy * 1024 + x];
                        float b  = img2[gy * 1024 + xe];
                        float cc = img2[yo * 1024 + x];
                        float d  = img2[yo * 1024 + xe];
                        r0[e] = a * a;
                        float t;
                        t = a - b;  r1[e] = t * t - r0[e];
                        t = a - cc; r2[e] = t * t - r0[e];
                        t = a - d;  r3[e] = t * t - r0[e];
                        float p  = img1[gy * 1024 + x];
                        float px = img1[gy * 1024 + xe];
                        float py = img1[yo * 1024 + x];
                        float u = p - px, w = p - py;
                        r4[e] = u * u + w * w + 2.f * p * p;
                    }
                }
                v0 = make_float4(r0[0], r0[1], r0[2], r0[3]);
                v1 = make_float4(r1[0], r1[1], r1[2], r1[3]);
                v2 = make_float4(r2[0], r2[1], r2[2], r2[3]);
                v3 = make_float4(r3[0], r3[1], r3[2], r3[3]);
                v4 = make_float4(r4[0], r4[1], r4[2], r4[3]);
            }
        }
        const int base = row * PITCH + c4;
        *(float4*)&sraw[0 * PSTR + base] = v0;
        *(float4*)&sraw[1 * PSTR + base] = v1;
        *(float4*)&sraw[2 * PSTR + base] = v2;
        *(float4*)&sraw[3 * PSTR + base] = v3;
        *(float4*)&sraw[4 * PSTR + base] = v4;
    }
    __syncthreads();

    if (xu && yu) {
        // ===================== FAST PATH =====================
        // ---- Phase A: rolling in-place vertical 7-tap (240 scalar threads) ----
        if (tid < 240) {
            const int pl = tid / PITCH;
            const int c = tid - pl * PITCH;
            const unsigned pb = pl * PSTR + c;
            float acc[7];
#pragma unroll
            for (int j = 0; j < 7; j++) acc[j] = 0.f;
#pragma unroll
            for (int i = 0; i < RIN; i++) {
                const float v = sraw[pb + i * PITCH];
#pragma unroll
                for (int d = 0; d < 7; d++) {
                    const int r = i - d;
                    if (r >= 0 && r < TY) acc[r % 7] += CW(d) * v;
                }
                if (i >= 6) {
                    const int r = i - 6;
                    sraw[pb + r * PITCH] = acc[r % 7];
                    acc[r % 7] = 0.f;
                }
            }
        }
        __syncthreads();

        // ---- Phase B: horizontal 7-tap (4 outputs/thread) + combine ----
        if (tid < 240) {
            const int y = tid / 10;
            const int x0 = (tid - y * 10) * 4;
            float rb0[4], rax[4], ray[4], rad[4], rs1[4];
#pragma unroll
            for (int p = 0; p < 5; p++) {
                float wv[12];
                const int rb = p * PSTR + y * PITCH + x0;
                *(float4*)&wv[0] = *(const float4*)&sraw[rb];
                *(float4*)&wv[4] = *(const float4*)&sraw[rb + 4];
                *(float4*)&wv[8] = *(const float4*)&sraw[rb + 8];
                float o0 = 0, o1 = 0, o2 = 0, o3 = 0;
#pragma unroll
                for (int k = 0; k < 7; k++) {
                    const float w = CW(k);
                    o0 += w * wv[k];     o1 += w * wv[k + 1];
                    o2 += w * wv[k + 2]; o3 += w * wv[k + 3];
                }
                if (p == 0)      { rb0[0]=o0; rb0[1]=o1; rb0[2]=o2; rb0[3]=o3; }
                else if (p == 1) { rax[0]=o0; rax[1]=o1; rax[2]=o2; rax[3]=o3; }
                else if (p == 2) { ray[0]=o0; ray[1]=o1; ray[2]=o2; ray[3]=o3; }
                else if (p == 3) { rad[0]=o0; rad[1]=o1; rad[2]=o2; rad[3]=o3; }
                else             { rs1[0]=o0; rs1[1]=o1; rs1[2]=o2; rs1[3]=o3; }
            }
            const int oy = by0 + y;
            if (oy <= 1017) {
#pragma unroll
                for (int j = 0; j < 4; j++) {
                    const int ox = bx0 + x0 + j;
                    if (ox <= 1016) {
                        float vimg = rs1[j] * 0.25f + 1e-5f;
                        float inv = __fdividef(-1.4426950408889634f, vimg);
                        float t0 = rb0[j] * inv;
                        float t1 = (rb0[j] + rax[j]) * inv;
                        float t2 = (rb0[j] + ray[j]) * inv;
                        float t3 = (rb0[j] + rad[j]) * inv;
                        float tm = fmaxf(fmaxf(t0, t1), fmaxf(t2, t3));
                        psum += 77.f * ex2(t0 - tm) + ex2(t1 - tm)
                                     + ex2(t2 - tm) + ex2(t3 - tm);
                    }
                }
            }
        }
    } else {
        // ===================== GENERAL PATH (512-boundary tiles) =====================
        const int rlo = 509 - by0;   // mixed output rows: [rlo, rlo+5]
        if (tid < 240) {
            const int pl = tid / PITCH;
            const int c = tid - pl * PITCH;
            const unsigned pb = pl * PSTR + c;
            const bool needT = (pl == 2 || pl == 3);
            float acc[7], accT[7], mbuf[6];
#pragma unroll
            for (int j = 0; j < 7; j++) { acc[j] = 0.f; accT[j] = 0.f; }
#pragma unroll
            for (int j = 0; j < 6; j++) mbuf[j] = 0.f;
#pragma unroll
            for (int i = 0; i < RIN; i++) {
                const float v = sraw[pb + i * PITCH];
                const float vT = (needT && (by0 - 3 + i) < 512) ? v : 0.f;
#pragma unroll
                for (int d = 0; d < 7; d++) {
                    const int r = i - d;
                    if (r >= 0 && r < TY) {
                        acc[r % 7]  += CW(d) * v;
                        accT[r % 7] += CW(d) * vT;
                    }
                }
                if (i >= 6) {
                    const int r = i - 6;
                    sraw[pb + r * PITCH] = acc[r % 7];
                    const int m = r - rlo;
                    if (m >= 0 && m < 6) mbuf[m] = accT[r % 7];
                    acc[r % 7] = 0.f; accT[r % 7] = 0.f;
                }
            }
            if (needT) {
                const int sb = (pl == 2 ? SPARE0 : SPARE1) + c;
#pragma unroll
                for (int m = 0; m < 6; m++) {
                    const int r = rlo + m;
                    if (r >= 0 && r < TY) sraw[sb + m * PITCH] = mbuf[m];
                }
            }
        }
        __syncthreads();

        if (tid < 240) {
            const int y = tid / 10;
            const int x0 = (tid - y * 10) * 4;
            const int oy = by0 + y;
#pragma unroll
            for (int j = 0; j < 4; j++) {
                const int x = x0 + j;
                const int ox = bx0 + x;
                float b0 = 0, hax = 0, haxL = 0, hay = 0;
                float had = 0, hadL = 0, hs1 = 0;
#pragma unroll
                for (int k = 0; k < 7; k++) {
                    const float w = CW(k);
                    const int cc = x + k;
                    const int yc = y * PITCH + cc;
                    bool left = (bx0 - 3 + cc) < 512;
                    b0 += w * sraw[0 * PSTR + yc];
                    float vx = w * sraw[1 * PSTR + yc]; hax += vx; haxL += left ? vx : 0.f;
                    hay += w * sraw[2 * PSTR + yc];
                    float vd = w * sraw[3 * PSTR + yc]; had += vd; hadL += left ? vd : 0.f;
                    hs1 += w * sraw[4 * PSTR + yc];
                }
                float hayt, hadt, hadtL;
                if (y < rlo) { hayt = hay; hadt = had; hadtL = hadL; }
                else if (y > rlo + 5) { hayt = 0.f; hadt = 0.f; hadtL = 0.f; }
                else {
                    const int m = y - rlo;
                    hayt = 0.f; hadt = 0.f; hadtL = 0.f;
#pragma unroll
                    for (int k = 0; k < 7; k++) {
                        const float w = CW(k);
                        const int cc = x + k;
                        bool left = (bx0 - 3 + cc) < 512;
                        hayt += w * sraw[SPARE0 + m * PITCH + cc];
                        float vt = w * sraw[SPARE1 + m * PITCH + cc];
                        hadt += vt; hadtL += left ? vt : 0.f;
                    }
                }
                if (oy <= 1017 && ox <= 1016) {
                    float vimg = hs1 * 0.25f + 1e-5f;
                    float inv = __fdividef(-1.4426950408889634f, vimg);
                    float D[9];
                    D[0] = b0;
                    D[1] = b0 + haxL;
                    D[2] = b0 + hax - haxL;
                    D[3] = b0 + hayt;
                    D[4] = b0 + hay - hayt;
                    D[5] = b0 + hadtL;
                    D[6] = b0 + hadt - hadtL;
                    D[7] = b0 + hadL - hadtL;
                    D[8] = b0 + (had - hadL) - (hadt - hadtL);
                    float t[9];
#pragma unroll
                    for (int c2 = 0; c2 < 9; c2++) t[c2] = D[c2] * inv;
                    float tm = t[0];
#pragma unroll
                    for (int c2 = 1; c2 < 9; c2++) tm = fmaxf(tm, t[c2]);
                    float s = 72.f * ex2(t[0] - tm);
#pragma unroll
                    for (int c2 = 1; c2 < 9; c2++) s += ex2(t[c2] - tm);
                    psum += s;
                }
            }
        }
    }

    // ---- deterministic block reduction (shuffle tree) ----
    float v = psum;
#pragma unroll
    for (int o2 = 16; o2 > 0; o2 >>= 1) v += __shfl_xor_sync(0xffffffffu, v, o2);
    if ((tid & 31) == 0) swr[tid >> 5] = v;
    __syncthreads();
    if (tid == 0) {
        float t = 0.f;
#pragma unroll
        for (int w = 0; w < 8; w++) t += swr[w];
        g_partials[blockIdx.y * NBX + blockIdx.x] = t;
        __threadfence();
        unsigned int n = atomicAdd(&g_count, 1u);
        s_last = (n == NBLK - 1);
    }
    __syncthreads();

    // ---- fused final reduction in the last-arriving block (fixed order) ----
    if (s_last) {
        float u = 0.f;
        for (int i = tid; i < NBLK; i += 256) u += g_partials[i];
#pragma unroll
        for (int o2 = 16; o2 > 0; o2 >>= 1) u += __shfl_xor_sync(0xffffffffu, u, o2);
        if ((tid & 31) == 0) swr[tid >> 5] = u;
        __syncthreads();
        if (tid == 0) {
            float t = 0.f;
#pragma unroll
            for (int w = 0; w < 8; w++) t += swr[w];
            out[0] = t * (float)(1.0 / 81688800.0);  // mean over 80*1011*1010
            g_count = 0;   // reset for next graph replay
        }
    }
}

extern "C" void kernel_launch(void* const* d_in, const int* in_sizes, int n_in,
                              void* d_out, int out_size) {
    const float* img1 = (const float*)d_in[0];
    const float* img2 = (const float*)d_in[1];
    dim3 grid(NBX, NBY);
    mind_main<<<grid, 256>>>(img1, img2, (float*)d_out);
}

// round 15
// speedup vs baseline: 1.3200x; 1.3200x over previous
#include <cuda_runtime.h>

// MIND loss, 1024x1024, round 15 = exact resubmission of round 6 (best measured:
// 19.2us). All structural variants since (bigger tiles, single-wave, fused
// loads, packed pairs, occupancy forcing) measured worse; locking the optimum.
//  - 72/80 channels identical; uniform tiles have only 4 distinct channels
//  - stage 5 basis planes (computed during LDG latency), plane stride 1224
//  - Phase A: rolling vertical 7-tap, thread=(plane,col), redundancy 1.0x
//  - Phase B: horizontal 7-tap, 4 outputs/thread, float4 smem reads
//  - deterministic shuffle reductions, fused last-block finish

#define TX 32
#define TY 24
#define NBX 32
#define NBY 43
#define NBLK (NBX * NBY)

#define PSTR 1224          // plane stride in floats (==8 mod 32, ==0 mod 4)
#define G2T  6120          // general-path scratch plane: a2t
#define G3T  7080          // general-path scratch plane: a3t

#define CW(k) ((k)==0 ? 0.06475879783294587f : \
               (k)==1 ? 0.12098536225957168f : \
               (k)==2 ? 0.17603266338214976f : \
               (k)==3 ? 0.19947114020071635f : \
               (k)==4 ? 0.17603266338214976f : \
               (k)==5 ? 0.12098536225957168f : \
                        0.06475879783294587f)

__device__ float g_partials[NBLK];
__device__ unsigned int g_count;

__device__ __forceinline__ float ex2(float x) {
    float r;
    asm("ex2.approx.ftz.f32 %0, %1;" : "=f"(r) : "f"(x));
    return r;
}

__global__ __launch_bounds__(256, 5)
void mind_main(const float* __restrict__ img1, const float* __restrict__ img2,
               float* __restrict__ out) {
    __shared__ float sraw[8064];
    __shared__ float swr[8];
    __shared__ bool s_last;

    const int tid = threadIdx.x;
    const int bx0 = 7 + blockIdx.x * TX;
    const int by0 = 7 + blockIdx.y * TY;

    const bool xu = !((bx0 - 3) < 512 && (bx0 + 34) >= 512);
    const bool yu = !((by0 - 3) < 512 && (by0 + 26) >= 512);

    float psum = 0.f;

    // ================= Stage basis fields (both paths) =================
    for (int i = tid; i < 300; i += 256) {
        const int row = i / 10;
        const int c4 = (i - row * 10) * 4;
        const int gy = by0 - 3 + row;
        const int gx = bx0 - 3 + c4;
        const int yo = gy ^ 512;
        const int xo = gx ^ 512;
        float4 v0 = {0,0,0,0}, v1 = v0, v2 = v0, v3 = v0, v4 = v0;
        if (gy < 1024) {
            if (gx + 3 < 1024) {
                float4 A  = *(const float4*)(img2 + gy * 1024 + gx);
                float4 B  = *(const float4*)(img2 + gy * 1024 + xo);
                float4 C  = *(const float4*)(img2 + yo * 1024 + gx);
                float4 D  = *(const float4*)(img2 + yo * 1024 + xo);
                float4 P  = *(const float4*)(img1 + gy * 1024 + gx);
                float4 Px = *(const float4*)(img1 + gy * 1024 + xo);
                float4 Py = *(const float4*)(img1 + yo * 1024 + gx);
                float t, u, w;
                v0.x = A.x * A.x; v0.y = A.y * A.y; v0.z = A.z * A.z; v0.w = A.w * A.w;
                t = A.x - B.x; v1.x = t * t - v0.x;  t = A.y - B.y; v1.y = t * t - v0.y;
                t = A.z - B.z; v1.z = t * t - v0.z;  t = A.w - B.w; v1.w = t * t - v0.w;
                t = A.x - C.x; v2.x = t * t - v0.x;  t = A.y - C.y; v2.y = t * t - v0.y;
                t = A.z - C.z; v2.z = t * t - v0.z;  t = A.w - C.w; v2.w = t * t - v0.w;
                t = A.x - D.x; v3.x = t * t - v0.x;  t = A.y - D.y; v3.y = t * t - v0.y;
                t = A.z - D.z; v3.z = t * t - v0.z;  t = A.w - D.w; v3.w = t * t - v0.w;
                u = P.x - Px.x; w = P.x - Py.x; v4.x = u * u + w * w + 2.f * P.x * P.x;
                u = P.y - Px.y; w = P.y - Py.y; v4.y = u * u + w * w + 2.f * P.y * P.y;
                u = P.z - Px.z; w = P.z - Py.z; v4.z = u * u + w * w + 2.f * P.z * P.z;
                u = P.w - Px.w; w = P.w - Py.w; v4.w = u * u + w * w + 2.f * P.w * P.w;
            } else {
                float r0[4], r1[4], r2[4], r3[4], r4[4];
#pragma unroll
                for (int e = 0; e < 4; e++) {
                    int x = gx + e;
                    r0[e] = r1[e] = r2[e] = r3[e] = r4[e] = 0.f;
                    if (x < 1024) {
                        int xe = x ^ 512;
                        float a  = img2[gy * 1024 + x];
                        float b  = img2[gy * 1024 + xe];
                        float cc = img2[yo * 1024 + x];
                        float d  = img2[yo * 1024 + xe];
                        r0[e] = a * a;
                        float t;
                        t = a - b;  r1[e] = t * t - r0[e];
                        t = a - cc; r2[e] = t * t - r0[e];
                        t = a - d;  r3[e] = t * t - r0[e];
                        float p  = img1[gy * 1024 + x];
                        float px = img1[gy * 1024 + xe];
                        float py = img1[yo * 1024 + x];
                        float u = p - px, w = p - py;
                        r4[e] = u * u + w * w + 2.f * p * p;
                    }
                }
                v0 = make_float4(r0[0], r0[1], r0[2], r0[3]);
                v1 = make_float4(r1[0], r1[1], r1[2], r1[3]);
                v2 = make_float4(r2[0], r2[1], r2[2], r2[3]);
                v3 = make_float4(r3[0], r3[1], r3[2], r3[3]);
                v4 = make_float4(r4[0], r4[1], r4[2], r4[3]);
            }
        }
        const int base = row * 40 + c4;
        *(float4*)&sraw[0 * PSTR + base] = v0;
        *(float4*)&sraw[1 * PSTR + base] = v1;
        *(float4*)&sraw[2 * PSTR + base] = v2;
        *(float4*)&sraw[3 * PSTR + base] = v3;
        *(float4*)&sraw[4 * PSTR + base] = v4;
    }
    __syncthreads();

    if (xu && yu) {
        // ===================== FAST PATH =====================
        // ---- Phase A: rolling vertical 7-tap, thread = (plane, col) ----
        float o[24];
        unsigned pb = 0;
        const bool act = tid < 200;
        if (act) {
            const int pl = tid / 40;
            const int cA = tid - pl * 40;
            pb = pl * PSTR + cA;
#pragma unroll
            for (int r = 0; r < 24; r++) o[r] = 0.f;
#pragma unroll
            for (int i = 0; i < 30; i++) {
                const float v = sraw[pb + i * 40];
#pragma unroll
                for (int d = 0; d < 7; d++) {
                    const int r = i - d;
                    if (r >= 0 && r < 24) o[r] += CW(d) * v;
                }
            }
        }
        __syncthreads();   // all staged reads done before overwrite
        if (act) {
#pragma unroll
            for (int r = 0; r < 24; r++) sraw[pb + r * 40] = o[r];
        }
        __syncthreads();

        // ---- Phase B: horizontal 7-tap (4 outputs/thread) + combine ----
        if (tid < 192) {
            const int seg = tid & 7;
            const int y = tid >> 3;
            const int x0 = seg * 4;
            float rb0[4], rax[4], ray[4], rad[4], rs1[4];
#pragma unroll
            for (int p = 0; p < 5; p++) {
                float wv[10];
                const int rb = p * PSTR + y * 40 + x0;
                *(float4*)&wv[0] = *(const float4*)&sraw[rb];
                *(float4*)&wv[4] = *(const float4*)&sraw[rb + 4];
                *(float2*)&wv[8] = *(const float2*)&sraw[rb + 8];
                float o0 = 0, o1 = 0, o2 = 0, o3 = 0;
#pragma unroll
                for (int k = 0; k < 7; k++) {
                    const float w = CW(k);
                    o0 += w * wv[k];     o1 += w * wv[k + 1];
                    o2 += w * wv[k + 2]; o3 += w * wv[k + 3];
                }
                if (p == 0)      { rb0[0]=o0; rb0[1]=o1; rb0[2]=o2; rb0[3]=o3; }
                else if (p == 1) { rax[0]=o0; rax[1]=o1; rax[2]=o2; rax[3]=o3; }
                else if (p == 2) { ray[0]=o0; ray[1]=o1; ray[2]=o2; ray[3]=o3; }
                else if (p == 3) { rad[0]=o0; rad[1]=o1; rad[2]=o2; rad[3]=o3; }
                else             { rs1[0]=o0; rs1[1]=o1; rs1[2]=o2; rs1[3]=o3; }
            }
            const int oy = by0 + y;
            if (oy <= 1017) {
#pragma unroll
                for (int j = 0; j < 4; j++) {
                    const int ox = bx0 + x0 + j;
                    if (ox <= 1016) {
                        float vimg = rs1[j] * 0.25f + 1e-5f;
                        float inv = __fdividef(-1.4426950408889634f, vimg);
                        float t0 = rb0[j] * inv;
                        float t1 = (rb0[j] + rax[j]) * inv;
                        float t2 = (rb0[j] + ray[j]) * inv;
                        float t3 = (rb0[j] + rad[j]) * inv;
                        float tm = fmaxf(fmaxf(t0, t1), fmaxf(t2, t3));
                        psum += 77.f * ex2(t0 - tm) + ex2(t1 - tm)
                                     + ex2(t2 - tm) + ex2(t3 - tm);
                    }
                }
            }
        }
    } else {
        // ===================== GENERAL PATH (512-boundary tiles) =====================
        // ---- Phase A: vertical 7-tap with top-masked variants ----
        const bool act = tid < 240;
        float a0[4], a1[4], a2[4], a2t[4], a3[4], a3t[4], a4[4];
        int cA = 0, gA = 0;
        if (act) {
            cA = tid % 40;
            gA = tid / 40;
#pragma unroll
            for (int j = 0; j < 4; j++) {
                a0[j]=0;a1[j]=0;a2[j]=0;a2t[j]=0;a3[j]=0;a3t[j]=0;a4[j]=0;
            }
#pragma unroll
            for (int i = 0; i < 10; i++) {
                const int row = gA * 4 + i;
                const int base = row * 40 + cA;
                float v0 = sraw[0 * PSTR + base];
                float v1 = sraw[1 * PSTR + base];
                float v2 = sraw[2 * PSTR + base];
                float v3 = sraw[3 * PSTR + base];
                float v4 = sraw[4 * PSTR + base];
                const bool top = (by0 - 3 + row) < 512;
                float v2t = top ? v2 : 0.f;
                float v3t = top ? v3 : 0.f;
#pragma unroll
                for (int j = 0; j < 4; j++) {
                    const int k = i - j;
                    if (k >= 0 && k < 7) {
                        const float w = CW(k);
                        a0[j] += w * v0;  a1[j] += w * v1;
                        a2[j] += w * v2;  a2t[j] += w * v2t;
                        a3[j] += w * v3;  a3t[j] += w * v3t;
                        a4[j] += w * v4;
                    }
                }
            }
        }
        __syncthreads();
        if (act) {
#pragma unroll
            for (int j = 0; j < 4; j++) {
                const int r = gA * 4 + j;
                const int rc = r * 40 + cA;
                sraw[0 * PSTR + rc] = a0[j];
                sraw[1 * PSTR + rc] = a1[j];
                sraw[2 * PSTR + rc] = a2[j];
                sraw[3 * PSTR + rc] = a3[j];
                sraw[4 * PSTR + rc] = a4[j];
                sraw[G2T + rc] = a2t[j];
                sraw[G3T + rc] = a3t[j];
            }
        }
        __syncthreads();

        // ---- Phase B: masked horizontal pass + 9-channel combine ----
        if (tid < 192) {
            const int seg = tid & 7;
            const int y = tid >> 3;
            const int oy = by0 + y;
#pragma unroll
            for (int j = 0; j < 4; j++) {
                const int x = seg * 4 + j;
                const int ox = bx0 + x;
                float b0 = 0, hax = 0, haxL = 0, hay = 0, hayt = 0;
                float had = 0, hadL = 0, hadt = 0, hadtL = 0, hs1 = 0;
#pragma unroll
                for (int k = 0; k < 7; k++) {
                    const float w = CW(k);
                    const int cc = x + k;
                    const int yc = y * 40 + cc;
                    bool left = (bx0 - 3 + cc) < 512;
                    b0 += w * sraw[0 * PSTR + yc];
                    float vx = w * sraw[1 * PSTR + yc]; hax += vx; haxL += left ? vx : 0.f;
                    hay  += w * sraw[2 * PSTR + yc];
                    hayt += w * sraw[G2T + yc];
                    float vd = w * sraw[3 * PSTR + yc]; had += vd; hadL += left ? vd : 0.f;
                    float vt = w * sraw[G3T + yc]; hadt += vt; hadtL += left ? vt : 0.f;
                    hs1 += w * sraw[4 * PSTR + yc];
                }
                if (oy <= 1017 && ox <= 1016) {
                    float vimg = hs1 * 0.25f + 1e-5f;
                    float inv = __fdividef(-1.4426950408889634f, vimg);
                    float D[9];
                    D[0] = b0;
                    D[1] = b0 + haxL;
                    D[2] = b0 + hax - haxL;
                    D[3] = b0 + hayt;
                    D[4] = b0 + hay - hayt;
                    D[5] = b0 + hadtL;
                    D[6] = b0 + hadt - hadtL;
                    D[7] = b0 + hadL - hadtL;
                    D[8] = b0 + (had - hadL) - (hadt - hadtL);
                    float t[9];
#pragma unroll
                    for (int c2 = 0; c2 < 9; c2++) t[c2] = D[c2] * inv;
                    float tm = t[0];
#pragma unroll
                    for (int c2 = 1; c2 < 9; c2++) tm = fmaxf(tm, t[c2]);
                    float s = 72.f * ex2(t[0] - tm);
#pragma unroll
                    for (int c2 = 1; c2 < 9; c2++) s += ex2(t[c2] - tm);
                    psum += s;
                }
            }
        }
    }

    // ---- deterministic block reduction (shuffle tree) ----
    float v = psum;
#pragma unroll
    for (int o2 = 16; o2 > 0; o2 >>= 1) v += __shfl_xor_sync(0xffffffffu, v, o2);
    if ((tid & 31) == 0) swr[tid >> 5] = v;
    __syncthreads();
    if (tid == 0) {
        float t = 0.f;
#pragma unroll
        for (int w = 0; w < 8; w++) t += swr[w];
        g_partials[blockIdx.y * NBX + blockIdx.x] = t;
        __threadfence();
        unsigned int n = atomicAdd(&g_count, 1u);
        s_last = (n == NBLK - 1);
    }
    __syncthreads();

    // ---- fused final reduction in the last-arriving block (fixed order) ----
    if (s_last) {
        float u = 0.f;
        for (int i = tid; i < NBLK; i += 256) u += g_partials[i];
#pragma unroll
        for (int o2 = 16; o2 > 0; o2 >>= 1) u += __shfl_xor_sync(0xffffffffu, u, o2);
        if ((tid & 31) == 0) swr[tid >> 5] = u;
        __syncthreads();
        if (tid == 0) {
            float t = 0.f;
#pragma unroll
            for (int w = 0; w < 8; w++) t += swr[w];
            out[0] = t * (float)(1.0 / 81688800.0);  // mean over 80*1011*1010
            g_count = 0;   // reset for next graph replay
        }
    }
}

extern "C" void kernel_launch(void* const* d_in, const int* in_sizes, int n_in,
                              void* d_out, int out_size) {
    const float* img1 = (const float*)d_in[0];
    const float* img2 = (const float*)d_in[1];
    dim3 grid(NBX, NBY);
    mind_main<<<grid, 256>>>(img1, img2, (float*)d_out);
}